// round 12
// baseline (speedup 1.0000x reference)
#include <cuda_runtime.h>
#include <cuda_bf16.h>

// ---------------- static scratch ----------------
__device__ int g_node_off[1025];

__global__ void k_prefix(const int* __restrict__ bn, int B) {
    if (threadIdx.x == 0) {
        int acc = 0;
        g_node_off[0] = 0;
        for (int i = 0; i < B; ++i) { acc += bn[i]; g_node_off[i + 1] = acc; }
    }
}

// ---------------- fast path ------------------------------------------------
// CTA = (graph, chunk); 4 warps, warp w owns 32-col slice [32w, 32w+32).
// Per-warp private smem accumulator: 64 segs x 32 floats (stride 32).
//
// R12: feature rows staged global->smem via cp.async.cg into a per-warp
// 4-deep ring (4KB/batch). MLP now register-free: wait_group(3) keeps 3
// batches (12KB) in flight per warp -- ~96KB/SM, >> the ~17KB needed for
// 8TB/s. Each lane cp.asyncs exactly the 16B it later LDS.128s back (lane
// (grp,slot) <-> row it*4+grp, bytes slot*16), so no cross-lane sync.
//   plan = xy-only warp intrinsics; also shfl-broadcasts inv into an
//          8-float reg array so rmw is shfl-free in the common path.
//   rmw  = 8x { LDS.128 data, LDS.128 acc, 4xFFMA(v,inv,a), STS.128 }.
#define FULLM 0xffffffffu
#define SSTAGES 4

struct Meta { int seg; float inv; };
struct Plan { unsigned sp0, sp1, pmask, cmask; };

__device__ __forceinline__ void cp16(float* smem_dst, const float* gsrc) {
    unsigned sdst = (unsigned)__cvta_generic_to_shared(smem_dst);
    asm volatile("cp.async.cg.shared.global [%0], [%1], 16;\n"
                 :: "r"(sdst), "l"(gsrc));
}
#define CP_COMMIT() asm volatile("cp.async.commit_group;\n" ::: "memory")
#define CP_WAIT3()  asm volatile("cp.async.wait_group 3;\n" ::: "memory")

__device__ __forceinline__ void load_xy(
    Meta& m, const int* __restrict__ xy, int base, int cend, int G, int lane)
{
    const int cnt = cend - base;                   // >= 1
    const int l   = (lane < cnt) ? lane : (cnt - 1);
    const int nd  = base + l;
    const int rr  = __ldg(&xy[3 * nd + 0]);
    const int cc  = __ldg(&xy[3 * nd + 1]);
    const int dv  = __ldg(&xy[3 * nd + 2]);
    m.seg = (lane < cnt) ? (rr * G + cc) : (64 + lane);   // marker never matches
    m.inv = 1.0f / (float)dv;
}

__device__ __forceinline__ void issue_feat(
    float* stage, const float* __restrict__ fbase, int base, int cend,
    int grp, int slot)
{
    const int cnt = cend - base;                   // may exceed 32
    #pragma unroll
    for (int it = 0; it < 8; ++it) {
        const int nb   = it * 4 + grp;
        const int node = base + ((nb < cnt) ? nb : (cnt - 1));
        cp16(stage + (it * 4 + grp) * 32 + slot * 4,
             fbase + (size_t)node * 128);
    }
}

__device__ __forceinline__ void plan_batch(
    Plan& P, float invs[8], const Meta& m,
    int base, int cend, int lane, int grp, unsigned below)
{
    const int cnt = (cend - base >= 32) ? 32 : (cend - base);
    unsigned pm = 0, s0 = 0, s1 = 0, cm = 0;

    #pragma unroll
    for (int it = 0; it < 8; ++it) {
        const int      nb     = it * 4 + grp;
        const int      seg    = __shfl_sync(FULLM, m.seg, nb);
        invs[it]              = __shfl_sync(FULLM, m.inv, nb);
        const unsigned mm     = __match_any_sync(FULLM, seg);
        const bool     leader = (mm & below) == 0u;
        const bool     act    = (nb < cnt);

        const unsigned sb = (unsigned)(seg & 63) << ((it & 3) * 8);
        if (it < 4) s0 |= sb; else s1 |= sb;
        if (act && leader) pm |= (1u << it);

        if (!__all_sync(FULLM, leader)) {              // warp-uniform
            pm |= (1u << (8 + it));
            const unsigned c1 = ((grp < 3) && ((mm >> ((lane + 8)  & 31)) & 1u)) ? 1u : 0u;
            const unsigned c2 = ((grp < 2) && ((mm >> ((lane + 16) & 31)) & 1u)) ? 2u : 0u;
            const unsigned c3 = ((grp < 1) && ((mm >> ((lane + 24) & 31)) & 1u)) ? 4u : 0u;
            cm |= (c1 | c2 | c3) << (it * 3);
        }
    }
    P.sp0 = s0; P.sp1 = s1; P.pmask = pm; P.cmask = cm;
}

__device__ __forceinline__ void rmw_batch(
    float* __restrict__ acc, const float* __restrict__ stage,
    const Plan& P, const float invs[8], int lane, int grp, int slot)
{
    #pragma unroll
    for (int it = 0; it < 8; ++it) {
        const unsigned sp  = (it < 4) ? P.sp0 : P.sp1;
        const int      seg = (sp >> ((it & 3) * 8)) & 0x3F;
        const bool lead = (P.pmask >> it) & 1u;
        const bool rare = (P.pmask >> (8 + it)) & 1u;    // warp-uniform
        const float inv = invs[it];

        const float4 v = *reinterpret_cast<const float4*>(
            stage + (it * 4 + grp) * 32 + slot * 4);
        float4* ap = reinterpret_cast<float4*>(acc + seg * 32 + slot * 4);

        if (!rare) {                                     // ~91%
            if (lead) {
                float4 a = *ap;
                a.x = fmaf(v.x, inv, a.x);
                a.y = fmaf(v.y, inv, a.y);
                a.z = fmaf(v.z, inv, a.z);
                a.w = fmaf(v.w, inv, a.w);
                *ap = a;
            }
        } else {                                         // donor merge
            float wx = v.x * inv, wy = v.y * inv, wz = v.z * inv, ww = v.w * inv;
            const float x1 = __shfl_down_sync(FULLM, wx, 8);
            const float y1 = __shfl_down_sync(FULLM, wy, 8);
            const float z1 = __shfl_down_sync(FULLM, wz, 8);
            const float w1 = __shfl_down_sync(FULLM, ww, 8);
            const float x2 = __shfl_down_sync(FULLM, wx, 16);
            const float y2 = __shfl_down_sync(FULLM, wy, 16);
            const float z2 = __shfl_down_sync(FULLM, wz, 16);
            const float w2 = __shfl_down_sync(FULLM, ww, 16);
            const float x3 = __shfl_down_sync(FULLM, wx, 24);
            const float y3 = __shfl_down_sync(FULLM, wy, 24);
            const float z3 = __shfl_down_sync(FULLM, wz, 24);
            const float w3 = __shfl_down_sync(FULLM, ww, 24);
            const unsigned cf = (P.cmask >> (it * 3)) & 7u;
            const bool c1 = cf & 1u, c2 = cf & 2u, c3 = cf & 4u;
            if (lead) {
                float4 a = *ap;
                a.x += wx + (c1 ? x1 : 0.f) + (c2 ? x2 : 0.f) + (c3 ? x3 : 0.f);
                a.y += wy + (c1 ? y1 : 0.f) + (c2 ? y2 : 0.f) + (c3 ? y3 : 0.f);
                a.z += wz + (c1 ? z1 : 0.f) + (c2 ? z2 : 0.f) + (c3 ? z3 : 0.f);
                a.w += ww + (c1 ? w1 : 0.f) + (c2 ? w2 : 0.f) + (c3 ? w3 : 0.f);
                *ap = a;
            }
        }
    }
}

// dynamic smem layout (floats):
//   [0 .. 8192)                acc: 4 warps x 64 segs x 32 cols   (32 KB)
//   [8192 .. 8192+4*4*1024)    staging: 4 warps x 4 stages x 1024 (64 KB)
__global__ void __launch_bounds__(128) spp_cpasync_kernel(
    const float* __restrict__ feat,
    const int*   __restrict__ xy,
    float*       __restrict__ out,
    int G, int C)
{
    extern __shared__ float smem[];

    const int t    = threadIdx.x;
    const int w    = t >> 5;
    const int lane = t & 31;
    const int grp  = lane >> 3;
    const int slot = lane & 7;
    const unsigned below = grp ? ((1u << (grp * 8)) - 1u) : 0u;

    const int g     = blockIdx.x / C;
    const int chunk = blockIdx.x % C;
    const int gbeg  = g_node_off[g];
    const int glen  = g_node_off[g + 1] - gbeg;
    const int cbeg  = gbeg + (int)((long long)glen * chunk / C);
    const int cend  = gbeg + (int)((long long)glen * (chunk + 1) / C);

    float* acc = smem + w * 2048;                       // 8KB per warp
    float* stw = smem + 8192 + w * (SSTAGES * 1024);    // 16KB per warp

    // zero own accumulator (warp-local; no CTA sync needed)
    float4* z = reinterpret_cast<float4*>(acc);
    #pragma unroll
    for (int i = lane; i < 512; i += 32) z[i] = make_float4(0.f, 0.f, 0.f, 0.f);
    __syncwarp();

    const float* fbase = feat + (size_t)w * 32 + (size_t)slot * 4;
    const int nb_total = (cend > cbeg) ? ((cend - cbeg + 31) >> 5) : 0;

    if (nb_total > 0) {
        // prologue: stage batches 0..SSTAGES-2 (always commit to keep count)
        #pragma unroll
        for (int k = 0; k < SSTAGES - 1; ++k) {
            if (k < nb_total)
                issue_feat(stw + k * 1024, fbase, cbeg + k * 32, cend, grp, slot);
            CP_COMMIT();
        }
        Meta Mc, Mn;
        load_xy(Mc, xy, cbeg, cend, G, lane);

        for (int b = 0; b < nb_total; ++b) {
            const int base = cbeg + b * 32;
            const int bi   = b + SSTAGES - 1;
            if (bi < nb_total)
                issue_feat(stw + (bi & (SSTAGES - 1)) * 1024, fbase,
                           cbeg + bi * 32, cend, grp, slot);
            CP_COMMIT();
            if (b + 1 < nb_total)
                load_xy(Mn, xy, base + 32, cend, G, lane);

            CP_WAIT3();                                  // batch b landed

            Plan P; float invs[8];
            plan_batch(P, invs, Mc, base, cend, lane, grp, below);
            rmw_batch(acc, stw + (b & (SSTAGES - 1)) * 1024, P, invs,
                      lane, grp, slot);
            Mc = Mn;
        }
    }
    __syncwarp();

    // epilogue: each warp flushes its own 8KB slice via RED.v4
    float* dstw = out + (size_t)g * 64 * 128 + (size_t)w * 32;
    #pragma unroll
    for (int i = lane; i < 512; i += 32) {
        const int seg = i >> 3, q = i & 7;
        float4 a = *reinterpret_cast<float4*>(acc + seg * 32 + q * 4);
        asm volatile("red.global.add.v4.f32 [%0], {%1, %2, %3, %4};"
                     :: "l"(dstw + (size_t)seg * 128 + q * 4),
                        "f"(a.x), "f"(a.y), "f"(a.z), "f"(a.w)
                     : "memory");
    }
}

// ---------------- fallback path (round-2 kernel) ----------------
__device__ __forceinline__ int find_graph(const int* s_off, int B, int node) {
    int lo = 0, hi = B;
    while (hi - lo > 1) {
        int mid = (lo + hi) >> 1;
        if (s_off[mid] <= node) lo = mid; else hi = mid;
    }
    return lo;
}

__global__ void __launch_bounds__(256) spp_pool_fallback(
    const float* __restrict__ feat, const int* __restrict__ xy,
    float* __restrict__ out, int N, int D, int G, int B)
{
    extern __shared__ int s_off[];
    for (int i = threadIdx.x; i <= B; i += blockDim.x) s_off[i] = g_node_off[i];
    __syncthreads();

    const int lane   = threadIdx.x & 31;
    const int warp   = (blockIdx.x * blockDim.x + threadIdx.x) >> 5;
    const int nwarps = (gridDim.x * blockDim.x) >> 5;

    for (long long base = (long long)warp * 32; base < N;
         base += (long long)nwarps * 32) {
        long long mynode = base + lane;
        int nd = (mynode < N) ? (int)mynode : (N - 1);
        const int r  = __ldg(&xy[3 * nd + 0]);
        const int c  = __ldg(&xy[3 * nd + 1]);
        const int dv = __ldg(&xy[3 * nd + 2]);
        int gid = find_graph(s_off, B, nd);
        const int   myseg = (gid * G + r) * G + c;
        const float myinv = 1.0f / (float)dv;
        const int cnt = (N - base >= 32) ? 32 : (int)(N - base);

        for (int j = 0; j < cnt; ++j) {
            const int   seg = __shfl_sync(0xffffffffu, myseg, j);
            const float inv = __shfl_sync(0xffffffffu, myinv, j);
            const float* src = feat + ((size_t)(base + j)) * D;
            for (int d4 = lane; d4 * 4 < D; d4 += 32) {
                float4 v = __ldg(reinterpret_cast<const float4*>(src) + d4);
                v.x *= inv; v.y *= inv; v.z *= inv; v.w *= inv;
                float* dst = out + (size_t)seg * D + d4 * 4;
                asm volatile("red.global.add.v4.f32 [%0], {%1, %2, %3, %4};"
                             :: "l"(dst), "f"(v.x), "f"(v.y), "f"(v.z), "f"(v.w)
                             : "memory");
            }
        }
    }
}

extern "C" void kernel_launch(void* const* d_in, const int* in_sizes, int n_in,
                              void* d_out, int out_size) {
    const float* feat = (const float*)d_in[0];
    const int*   xy   = (const int*)d_in[1];
    const int*   bn   = (const int*)d_in[2];
    float*       out  = (float*)d_out;

    const int B = in_sizes[2];
    const int N = in_sizes[1] / 3;
    const int D = in_sizes[0] / N;
    const int S = out_size / D;        // B*G*G
    const int gg = S / B;
    int G = 1;
    while (G * G < gg) ++G;

    k_prefix<<<1, 32>>>(bn, B);

    // output accumulated via RED in both paths -> zero every replay
    cudaMemsetAsync(d_out, 0, (size_t)out_size * sizeof(float), 0);

    const bool fast = (D == 128) && (gg == 64) && (G == 8) &&
                      (S == B * 64) && (B <= 1024);

    if (fast) {
        const size_t smem_bytes = (8192 + 4 * SSTAGES * 1024) * sizeof(float); // 96KB
        static bool attr_set = false;
        if (!attr_set) {
            cudaFuncSetAttribute(spp_cpasync_kernel,
                                 cudaFuncAttributeMaxDynamicSharedMemorySize,
                                 (int)smem_bytes);
            attr_set = true;
        }
        int C = (576 + B - 1) / B;     // ~576 CTAs (2/SM, ~2 balanced waves)
        if (C < 1) C = 1;
        spp_cpasync_kernel<<<B * C, 128, smem_bytes>>>(feat, xy, out, G, C);
    } else {
        size_t smem = (size_t)(B + 1) * sizeof(int);
        long long batches = ((long long)N + 31) / 32;
        int blocks = (int)((batches + 7) / 8);
        if (blocks > 65535) blocks = 65535;
        spp_pool_fallback<<<blocks, 256, smem>>>(feat, xy, out, N, D, G, B);
    }
}

// round 13
// speedup vs baseline: 1.7589x; 1.7589x over previous
#include <cuda_runtime.h>
#include <cuda_bf16.h>

// ---------------- static scratch ----------------
__device__ int g_node_off[1025];

__global__ void k_prefix(const int* __restrict__ bn, int B) {
    if (threadIdx.x == 0) {
        int acc = 0;
        g_node_off[0] = 0;
        for (int i = 0; i < B; ++i) { acc += bn[i]; g_node_off[i + 1] = acc; }
    }
}

// ---------------- fast path (R9 structure, 6 CTAs/SM) ------------------------
// CTA = (graph, chunk); 4 warps, warp w owns 32-col slice [32w, 32w+32).
// Every warp walks all 32-node batches of the chunk.
// Per-warp private accumulator: 64 segs x 32 floats (stride 32, conflict-free).
// Pipeline: load(b+1) -> rmw(b) -> meta(b+1).
//   load = LDG issue only (xy meta + 8x LDG.128 feature rows, streaming hint)
//   meta = all warp intrinsics (shfl, match, vote, donor merge, scaling)
//   rmw  = 8x predicated {LDS.128, 4xFADD, STS.128}
// R13: __launch_bounds__(128, 6) caps regs at 85 (live-state audit ~88 with
// slack at 96) -> 24 warps/SM vs 19; DRAM equilibrium moves up.
#define FULLM 0xffffffffu

struct Batch {
    int      seg;        // this lane's node seg (64+lane marker if inactive)
    float    inv;
    float4   vv[8];      // after meta: scaled + donor-merged
    unsigned sp0, sp1;   // after meta: segs of iters 0..3 / 4..7, 8b each
    unsigned pmask;      // after meta: bit it = (active && leader)
};

__device__ __forceinline__ float4 ldcs4(const float4* p) {
    float4 v;
    asm volatile("ld.global.cs.v4.f32 {%0, %1, %2, %3}, [%4];"
                 : "=f"(v.x), "=f"(v.y), "=f"(v.z), "=f"(v.w) : "l"(p));
    return v;
}

__device__ __forceinline__ void load_batch(
    Batch& b, const int* __restrict__ xy, const float* __restrict__ fbase,
    int base, int cend, int G, int lane, int grp)
{
    const int cnt = cend - base;                   // >= 1 (may exceed 32)
    const int l   = (lane < cnt) ? lane : (cnt - 1);
    const int nd  = base + l;
    const int rr  = __ldg(&xy[3 * nd + 0]);
    const int cc  = __ldg(&xy[3 * nd + 1]);
    const int dv  = __ldg(&xy[3 * nd + 2]);
    b.seg = (lane < cnt) ? (rr * G + cc) : (64 + lane);  // marker never matches
    b.inv = 1.0f / (float)dv;

    #pragma unroll
    for (int it = 0; it < 8; ++it) {
        const int nb   = it * 4 + grp;
        const int node = base + ((nb < cnt) ? nb : (cnt - 1));
        b.vv[it] = ldcs4(reinterpret_cast<const float4*>(fbase + (size_t)node * 128));
    }
}

__device__ __forceinline__ void meta_batch(
    Batch& b, int base, int cend, int lane, int grp, unsigned below)
{
    const int cnt = (cend - base >= 32) ? 32 : (cend - base);
    unsigned pm = 0, s0 = 0, s1 = 0;

    #pragma unroll
    for (int it = 0; it < 8; ++it) {
        const int   nb  = it * 4 + grp;
        const int   seg = __shfl_sync(FULLM, b.seg, nb);
        const float inv = __shfl_sync(FULLM, b.inv, nb);
        const bool  act = (nb < cnt);

        float4 wv = b.vv[it];
        wv.x *= inv; wv.y *= inv; wv.z *= inv; wv.w *= inv;

        const unsigned mm     = __match_any_sync(FULLM, seg);
        const bool     leader = (mm & below) == 0u;

        if (!__all_sync(FULLM, leader)) {          // ~9%: donor merge
            const float x1 = __shfl_down_sync(FULLM, wv.x, 8);
            const float y1 = __shfl_down_sync(FULLM, wv.y, 8);
            const float z1 = __shfl_down_sync(FULLM, wv.z, 8);
            const float w1 = __shfl_down_sync(FULLM, wv.w, 8);
            const float x2 = __shfl_down_sync(FULLM, wv.x, 16);
            const float y2 = __shfl_down_sync(FULLM, wv.y, 16);
            const float z2 = __shfl_down_sync(FULLM, wv.z, 16);
            const float w2 = __shfl_down_sync(FULLM, wv.w, 16);
            const float x3 = __shfl_down_sync(FULLM, wv.x, 24);
            const float y3 = __shfl_down_sync(FULLM, wv.y, 24);
            const float z3 = __shfl_down_sync(FULLM, wv.z, 24);
            const float w3 = __shfl_down_sync(FULLM, wv.w, 24);

            const bool c1 = (grp < 3) && ((mm >> ((lane + 8)  & 31)) & 1u);
            const bool c2 = (grp < 2) && ((mm >> ((lane + 16) & 31)) & 1u);
            const bool c3 = (grp < 1) && ((mm >> ((lane + 24) & 31)) & 1u);

            wv.x += (c1 ? x1 : 0.f) + (c2 ? x2 : 0.f) + (c3 ? x3 : 0.f);
            wv.y += (c1 ? y1 : 0.f) + (c2 ? y2 : 0.f) + (c3 ? y3 : 0.f);
            wv.z += (c1 ? z1 : 0.f) + (c2 ? z2 : 0.f) + (c3 ? z3 : 0.f);
            wv.w += (c1 ? w1 : 0.f) + (c2 ? w2 : 0.f) + (c3 ? w3 : 0.f);
        }
        b.vv[it] = wv;

        const unsigned sb = (unsigned)(seg & 63) << ((it & 3) * 8);
        if (it < 4) s0 |= sb; else s1 |= sb;
        if (act && leader) pm |= (1u << it);
    }
    b.sp0 = s0; b.sp1 = s1; b.pmask = pm;
}

__device__ __forceinline__ void rmw_batch(
    float* __restrict__ acc, const Batch& b, int slot)
{
    #pragma unroll
    for (int it = 0; it < 8; ++it) {
        if (b.pmask & (1u << it)) {
            const unsigned sp  = (it < 4) ? b.sp0 : b.sp1;
            const int      seg = (sp >> ((it & 3) * 8)) & 0xFF;
            float4* ap = reinterpret_cast<float4*>(acc + seg * 32 + slot * 4);
            float4 a = *ap;
            const float4 v = b.vv[it];
            a.x += v.x; a.y += v.y; a.z += v.z; a.w += v.w;
            *ap = a;
        }
    }
}

__global__ void __launch_bounds__(128, 6) spp_pipe_kernel(
    const float* __restrict__ feat,
    const int*   __restrict__ xy,
    float*       __restrict__ out,
    int G, int C)
{
    __shared__ float s_acc[4 * 64 * 32];           // 32 KB, stride 32 (no pad)

    const int t    = threadIdx.x;
    const int w    = t >> 5;                       // warp = 32-col slice
    const int lane = t & 31;
    const int grp  = lane >> 3;                    // node group 0..3
    const int slot = lane & 7;                     // float4 slot 0..7
    const unsigned below = grp ? ((1u << (grp * 8)) - 1u) : 0u;

    const int g     = blockIdx.x / C;
    const int chunk = blockIdx.x % C;
    const int gbeg  = g_node_off[g];
    const int glen  = g_node_off[g + 1] - gbeg;
    const int cbeg  = gbeg + (int)((long long)glen * chunk / C);
    const int cend  = gbeg + (int)((long long)glen * (chunk + 1) / C);

    // zero accumulators
    float4* z = reinterpret_cast<float4*>(s_acc);
    #pragma unroll
    for (int i = t; i < 4 * 64 * 8; i += 128) z[i] = make_float4(0.f, 0.f, 0.f, 0.f);
    __syncthreads();

    float* acc = s_acc + w * 64 * 32;
    const float* fbase = feat + (size_t)w * 32 + (size_t)slot * 4;

    // pipeline: load(b+1) -> rmw(b) -> meta(b+1)
    Batch A, B2;
    int base = cbeg;
    if (base < cend) {
        load_batch(A, xy, fbase, base, cend, G, lane, grp);
        meta_batch(A, base, cend, lane, grp, below);
        for (;;) {
            const int base2 = base + 32;
            if (base2 < cend) {
                load_batch(B2, xy, fbase, base2, cend, G, lane, grp);
                rmw_batch(acc, A, slot);
                meta_batch(B2, base2, cend, lane, grp, below);
                const int base3 = base2 + 32;
                if (base3 < cend) {
                    load_batch(A, xy, fbase, base3, cend, G, lane, grp);
                    rmw_batch(acc, B2, slot);
                    meta_batch(A, base3, cend, lane, grp, below);
                    base = base3;
                    continue;
                }
                rmw_batch(acc, B2, slot);
                break;
            }
            rmw_batch(acc, A, slot);
            break;
        }
    }
    __syncwarp();

    // epilogue: each warp flushes its own 8KB slice via RED.v4
    float* dstw = out + (size_t)g * 64 * 128 + (size_t)w * 32;
    #pragma unroll
    for (int i = lane; i < 512; i += 32) {
        const int seg = i >> 3, q = i & 7;
        float4 a = *reinterpret_cast<float4*>(acc + seg * 32 + q * 4);
        asm volatile("red.global.add.v4.f32 [%0], {%1, %2, %3, %4};"
                     :: "l"(dstw + (size_t)seg * 128 + q * 4),
                        "f"(a.x), "f"(a.y), "f"(a.z), "f"(a.w)
                     : "memory");
    }
}

// ---------------- fallback path (round-2 kernel) ----------------
__device__ __forceinline__ int find_graph(const int* s_off, int B, int node) {
    int lo = 0, hi = B;
    while (hi - lo > 1) {
        int mid = (lo + hi) >> 1;
        if (s_off[mid] <= node) lo = mid; else hi = mid;
    }
    return lo;
}

__global__ void __launch_bounds__(256) spp_pool_fallback(
    const float* __restrict__ feat, const int* __restrict__ xy,
    float* __restrict__ out, int N, int D, int G, int B)
{
    extern __shared__ int s_off[];
    for (int i = threadIdx.x; i <= B; i += blockDim.x) s_off[i] = g_node_off[i];
    __syncthreads();

    const int lane   = threadIdx.x & 31;
    const int warp   = (blockIdx.x * blockDim.x + threadIdx.x) >> 5;
    const int nwarps = (gridDim.x * blockDim.x) >> 5;

    for (long long base = (long long)warp * 32; base < N;
         base += (long long)nwarps * 32) {
        long long mynode = base + lane;
        int nd = (mynode < N) ? (int)mynode : (N - 1);
        const int r  = __ldg(&xy[3 * nd + 0]);
        const int c  = __ldg(&xy[3 * nd + 1]);
        const int dv = __ldg(&xy[3 * nd + 2]);
        int gid = find_graph(s_off, B, nd);
        const int   myseg = (gid * G + r) * G + c;
        const float myinv = 1.0f / (float)dv;
        const int cnt = (N - base >= 32) ? 32 : (int)(N - base);

        for (int j = 0; j < cnt; ++j) {
            const int   seg = __shfl_sync(0xffffffffu, myseg, j);
            const float inv = __shfl_sync(0xffffffffu, myinv, j);
            const float* src = feat + ((size_t)(base + j)) * D;
            for (int d4 = lane; d4 * 4 < D; d4 += 32) {
                float4 v = __ldg(reinterpret_cast<const float4*>(src) + d4);
                v.x *= inv; v.y *= inv; v.z *= inv; v.w *= inv;
                float* dst = out + (size_t)seg * D + d4 * 4;
                asm volatile("red.global.add.v4.f32 [%0], {%1, %2, %3, %4};"
                             :: "l"(dst), "f"(v.x), "f"(v.y), "f"(v.z), "f"(v.w)
                             : "memory");
            }
        }
    }
}

extern "C" void kernel_launch(void* const* d_in, const int* in_sizes, int n_in,
                              void* d_out, int out_size) {
    const float* feat = (const float*)d_in[0];
    const int*   xy   = (const int*)d_in[1];
    const int*   bn   = (const int*)d_in[2];
    float*       out  = (float*)d_out;

    const int B = in_sizes[2];
    const int N = in_sizes[1] / 3;
    const int D = in_sizes[0] / N;
    const int S = out_size / D;        // B*G*G
    const int gg = S / B;
    int G = 1;
    while (G * G < gg) ++G;

    k_prefix<<<1, 32>>>(bn, B);

    // output accumulated via RED in both paths -> zero every replay
    cudaMemsetAsync(d_out, 0, (size_t)out_size * sizeof(float), 0);

    const bool fast = (D == 128) && (gg == 64) && (G == 8) &&
                      (S == B * 64) && (B <= 1024);

    if (fast) {
        int C = 832 / B;               // single wave at 6 CTAs/SM (B=64 -> 13)
        if (C < 1) C = 1;
        spp_pipe_kernel<<<B * C, 128>>>(feat, xy, out, G, C);
    } else {
        size_t smem = (size_t)(B + 1) * sizeof(int);
        long long batches = ((long long)N + 31) / 32;
        int blocks = (int)((batches + 7) / 8);
        if (blocks > 65535) blocks = 65535;
        spp_pool_fallback<<<blocks, 256, smem>>>(feat, xy, out, N, D, G, B);
    }
}

// round 14
// speedup vs baseline: 2.0185x; 1.1476x over previous
#include <cuda_runtime.h>
#include <cuda_bf16.h>

// ---------------- static scratch ----------------
__device__ int g_node_off[1025];

__global__ void k_prefix(const int* __restrict__ bn, int B) {
    if (threadIdx.x == 0) {
        int acc = 0;
        g_node_off[0] = 0;
        for (int i = 0; i < B; ++i) { acc += bn[i]; g_node_off[i + 1] = acc; }
    }
}

// ---------------- fast path (R9 + distance-2 xy prefetch + ldcs) -----------
// CTA = (graph, chunk); 4 warps, warp w owns 32-col slice [32w, 32w+32).
// Every warp walks all 32-node batches of the chunk.
// Per-warp private accumulator: 64 segs x 32 floats (stride 32, conflict-free).
// Pipeline: load_feat(b+1) + load_xy(b+2) -> rmw(b) -> meta(b+1).
#define FULLM 0xffffffffu

struct Meta { int seg; float inv; };

struct Batch {
    int      seg;        // this lane's node seg (64+lane marker if inactive)
    float    inv;
    float4   vv[8];      // after meta: scaled + donor-merged
    unsigned sp0, sp1;   // after meta: segs of iters 0..3 / 4..7, 8b each
    unsigned pmask;      // after meta: bit it = (active && leader)
};

__device__ __forceinline__ float4 ldcs4(const float4* p) {
    float4 v;
    asm volatile("ld.global.cs.v4.f32 {%0, %1, %2, %3}, [%4];"
                 : "=f"(v.x), "=f"(v.y), "=f"(v.z), "=f"(v.w) : "l"(p));
    return v;
}

__device__ __forceinline__ Meta load_xy(
    const int* __restrict__ xy, int base, int cend, int G, int lane)
{
    Meta m;
    const int cnt = cend - base;                   // >= 1
    const int l   = (lane < cnt) ? lane : (cnt - 1);
    const int nd  = base + l;
    const int rr  = __ldg(&xy[3 * nd + 0]);
    const int cc  = __ldg(&xy[3 * nd + 1]);
    const int dv  = __ldg(&xy[3 * nd + 2]);
    m.seg = (lane < cnt) ? (rr * G + cc) : (64 + lane);   // marker never matches
    m.inv = 1.0f / (float)dv;
    return m;
}

__device__ __forceinline__ void load_feat(
    Batch& b, const float* __restrict__ fbase, int base, int cend, int grp)
{
    const int cnt = cend - base;
    #pragma unroll
    for (int it = 0; it < 8; ++it) {
        const int nb   = it * 4 + grp;
        const int node = base + ((nb < cnt) ? nb : (cnt - 1));
        b.vv[it] = ldcs4(reinterpret_cast<const float4*>(fbase + (size_t)node * 128));
    }
}

__device__ __forceinline__ void meta_batch(
    Batch& b, int base, int cend, int lane, int grp, unsigned below)
{
    const int cnt = (cend - base >= 32) ? 32 : (cend - base);
    unsigned pm = 0, s0 = 0, s1 = 0;

    #pragma unroll
    for (int it = 0; it < 8; ++it) {
        const int   nb  = it * 4 + grp;
        const int   seg = __shfl_sync(FULLM, b.seg, nb);
        const float inv = __shfl_sync(FULLM, b.inv, nb);
        const bool  act = (nb < cnt);

        float4 wv = b.vv[it];
        wv.x *= inv; wv.y *= inv; wv.z *= inv; wv.w *= inv;

        const unsigned mm     = __match_any_sync(FULLM, seg);
        const bool     leader = (mm & below) == 0u;

        if (!__all_sync(FULLM, leader)) {          // ~9%: donor merge
            const float x1 = __shfl_down_sync(FULLM, wv.x, 8);
            const float y1 = __shfl_down_sync(FULLM, wv.y, 8);
            const float z1 = __shfl_down_sync(FULLM, wv.z, 8);
            const float w1 = __shfl_down_sync(FULLM, wv.w, 8);
            const float x2 = __shfl_down_sync(FULLM, wv.x, 16);
            const float y2 = __shfl_down_sync(FULLM, wv.y, 16);
            const float z2 = __shfl_down_sync(FULLM, wv.z, 16);
            const float w2 = __shfl_down_sync(FULLM, wv.w, 16);
            const float x3 = __shfl_down_sync(FULLM, wv.x, 24);
            const float y3 = __shfl_down_sync(FULLM, wv.y, 24);
            const float z3 = __shfl_down_sync(FULLM, wv.z, 24);
            const float w3 = __shfl_down_sync(FULLM, wv.w, 24);

            const bool c1 = (grp < 3) && ((mm >> ((lane + 8)  & 31)) & 1u);
            const bool c2 = (grp < 2) && ((mm >> ((lane + 16) & 31)) & 1u);
            const bool c3 = (grp < 1) && ((mm >> ((lane + 24) & 31)) & 1u);

            wv.x += (c1 ? x1 : 0.f) + (c2 ? x2 : 0.f) + (c3 ? x3 : 0.f);
            wv.y += (c1 ? y1 : 0.f) + (c2 ? y2 : 0.f) + (c3 ? y3 : 0.f);
            wv.z += (c1 ? z1 : 0.f) + (c2 ? z2 : 0.f) + (c3 ? z3 : 0.f);
            wv.w += (c1 ? w1 : 0.f) + (c2 ? w2 : 0.f) + (c3 ? w3 : 0.f);
        }
        b.vv[it] = wv;

        const unsigned sb = (unsigned)(seg & 63) << ((it & 3) * 8);
        if (it < 4) s0 |= sb; else s1 |= sb;
        if (act && leader) pm |= (1u << it);
    }
    b.sp0 = s0; b.sp1 = s1; b.pmask = pm;
}

__device__ __forceinline__ void rmw_batch(
    float* __restrict__ acc, const Batch& b, int slot)
{
    #pragma unroll
    for (int it = 0; it < 8; ++it) {
        if (b.pmask & (1u << it)) {
            const unsigned sp  = (it < 4) ? b.sp0 : b.sp1;
            const int      seg = (sp >> ((it & 3) * 8)) & 0xFF;
            float4* ap = reinterpret_cast<float4*>(acc + seg * 32 + slot * 4);
            float4 a = *ap;
            const float4 v = b.vv[it];
            a.x += v.x; a.y += v.y; a.z += v.z; a.w += v.w;
            *ap = a;
        }
    }
}

__global__ void __launch_bounds__(128, 5) spp_pipe_kernel(
    const float* __restrict__ feat,
    const int*   __restrict__ xy,
    float*       __restrict__ out,
    int G, int C)
{
    __shared__ float s_acc[4 * 64 * 32];           // 32 KB, stride 32 (no pad)

    const int t    = threadIdx.x;
    const int w    = t >> 5;                       // warp = 32-col slice
    const int lane = t & 31;
    const int grp  = lane >> 3;                    // node group 0..3
    const int slot = lane & 7;                     // float4 slot 0..7
    const unsigned below = grp ? ((1u << (grp * 8)) - 1u) : 0u;

    const int g     = blockIdx.x / C;
    const int chunk = blockIdx.x % C;
    const int gbeg  = g_node_off[g];
    const int glen  = g_node_off[g + 1] - gbeg;
    const int cbeg  = gbeg + (int)((long long)glen * chunk / C);
    const int cend  = gbeg + (int)((long long)glen * (chunk + 1) / C);

    // zero accumulators
    float4* z = reinterpret_cast<float4*>(s_acc);
    #pragma unroll
    for (int i = t; i < 4 * 64 * 8; i += 128) z[i] = make_float4(0.f, 0.f, 0.f, 0.f);
    __syncthreads();

    float* acc = s_acc + w * 64 * 32;
    const float* fbase = feat + (size_t)w * 32 + (size_t)slot * 4;

    // pipeline: load_feat(b+1) + load_xy(b+2) -> rmw(b) -> meta(b+1)
    Batch A, B2;
    Meta  M0, M1;                                  // xy meta, distance-2 ring
    int p = cbeg;
    if (p < cend) {
        M0 = load_xy(xy, p, cend, G, lane);
        M1 = (p + 32 < cend) ? load_xy(xy, p + 32, cend, G, lane) : M0;
        A.seg = M0.seg; A.inv = M0.inv;
        load_feat(A, fbase, p, cend, grp);
        meta_batch(A, p, cend, lane, grp, below);
        for (;;) {
            const int p1 = p + 32;
            if (p1 < cend) {
                B2.seg = M1.seg; B2.inv = M1.inv;
                load_feat(B2, fbase, p1, cend, grp);
                if (p1 + 32 < cend)
                    M0 = load_xy(xy, p1 + 32, cend, G, lane);
                rmw_batch(acc, A, slot);
                meta_batch(B2, p1, cend, lane, grp, below);
                const int p2 = p1 + 32;
                if (p2 < cend) {
                    A.seg = M0.seg; A.inv = M0.inv;
                    load_feat(A, fbase, p2, cend, grp);
                    if (p2 + 32 < cend)
                        M1 = load_xy(xy, p2 + 32, cend, G, lane);
                    rmw_batch(acc, B2, slot);
                    meta_batch(A, p2, cend, lane, grp, below);
                    p = p2;
                    continue;
                }
                rmw_batch(acc, B2, slot);
                break;
            }
            rmw_batch(acc, A, slot);
            break;
        }
    }
    __syncwarp();

    // epilogue: each warp flushes its own 8KB slice via RED.v4
    float* dstw = out + (size_t)g * 64 * 128 + (size_t)w * 32;
    #pragma unroll
    for (int i = lane; i < 512; i += 32) {
        const int seg = i >> 3, q = i & 7;
        float4 a = *reinterpret_cast<float4*>(acc + seg * 32 + q * 4);
        asm volatile("red.global.add.v4.f32 [%0], {%1, %2, %3, %4};"
                     :: "l"(dstw + (size_t)seg * 128 + q * 4),
                        "f"(a.x), "f"(a.y), "f"(a.z), "f"(a.w)
                     : "memory");
    }
}

// ---------------- fallback path (round-2 kernel) ----------------
__device__ __forceinline__ int find_graph(const int* s_off, int B, int node) {
    int lo = 0, hi = B;
    while (hi - lo > 1) {
        int mid = (lo + hi) >> 1;
        if (s_off[mid] <= node) lo = mid; else hi = mid;
    }
    return lo;
}

__global__ void __launch_bounds__(256) spp_pool_fallback(
    const float* __restrict__ feat, const int* __restrict__ xy,
    float* __restrict__ out, int N, int D, int G, int B)
{
    extern __shared__ int s_off[];
    for (int i = threadIdx.x; i <= B; i += blockDim.x) s_off[i] = g_node_off[i];
    __syncthreads();

    const int lane   = threadIdx.x & 31;
    const int warp   = (blockIdx.x * blockDim.x + threadIdx.x) >> 5;
    const int nwarps = (gridDim.x * blockDim.x) >> 5;

    for (long long base = (long long)warp * 32; base < N;
         base += (long long)nwarps * 32) {
        long long mynode = base + lane;
        int nd = (mynode < N) ? (int)mynode : (N - 1);
        const int r  = __ldg(&xy[3 * nd + 0]);
        const int c  = __ldg(&xy[3 * nd + 1]);
        const int dv = __ldg(&xy[3 * nd + 2]);
        int gid = find_graph(s_off, B, nd);
        const int   myseg = (gid * G + r) * G + c;
        const float myinv = 1.0f / (float)dv;
        const int cnt = (N - base >= 32) ? 32 : (int)(N - base);

        for (int j = 0; j < cnt; ++j) {
            const int   seg = __shfl_sync(0xffffffffu, myseg, j);
            const float inv = __shfl_sync(0xffffffffu, myinv, j);
            const float* src = feat + ((size_t)(base + j)) * D;
            for (int d4 = lane; d4 * 4 < D; d4 += 32) {
                float4 v = __ldg(reinterpret_cast<const float4*>(src) + d4);
                v.x *= inv; v.y *= inv; v.z *= inv; v.w *= inv;
                float* dst = out + (size_t)seg * D + d4 * 4;
                asm volatile("red.global.add.v4.f32 [%0], {%1, %2, %3, %4};"
                             :: "l"(dst), "f"(v.x), "f"(v.y), "f"(v.z), "f"(v.w)
                             : "memory");
            }
        }
    }
}

extern "C" void kernel_launch(void* const* d_in, const int* in_sizes, int n_in,
                              void* d_out, int out_size) {
    const float* feat = (const float*)d_in[0];
    const int*   xy   = (const int*)d_in[1];
    const int*   bn   = (const int*)d_in[2];
    float*       out  = (float*)d_out;

    const int B = in_sizes[2];
    const int N = in_sizes[1] / 3;
    const int D = in_sizes[0] / N;
    const int S = out_size / D;        // B*G*G
    const int gg = S / B;
    int G = 1;
    while (G * G < gg) ++G;

    k_prefix<<<1, 32>>>(bn, B);

    // output accumulated via RED in both paths -> zero every replay
    cudaMemsetAsync(d_out, 0, (size_t)out_size * sizeof(float), 0);

    const bool fast = (D == 128) && (gg == 64) && (G == 8) &&
                      (S == B * 64) && (B <= 1024);

    if (fast) {
        int C = 704 / B;               // single wave at 5 CTAs/SM (B=64 -> 11)
        if (C < 1) C = 1;
        spp_pipe_kernel<<<B * C, 128>>>(feat, xy, out, G, C);
    } else {
        size_t smem = (size_t)(B + 1) * sizeof(int);
        long long batches = ((long long)N + 31) / 32;
        int blocks = (int)((batches + 7) / 8);
        if (blocks > 65535) blocks = 65535;
        spp_pool_fallback<<<blocks, 256, smem>>>(feat, xy, out, N, D, G, B);
    }
}